// round 3
// baseline (speedup 1.0000x reference)
#include <cuda_runtime.h>
#include <cuda_bf16.h>

#define BB 4
#define TT 4096
#define DD 768
#define HH 64
#define BT (BB*TT)

// Scratch for projected Q, K, V (fp32).
__device__ float g_Q[BT * HH];
__device__ float g_K[BT * HH];
__device__ float g_V[BT * HH];

// ---------------------------------------------------------------------------
// Kernel 1: fused QKV projection.  C[m] = x @ W[m], x:[BT,768], W:[768,64].
// BM=128 rows, all 192 cols (Q|K|V). 256 threads: 16x16 grid, microtile
// 8 rows x (3 mats x 4 cols) = 96 acc. 0.83 smem bytes per FMA.
// ---------------------------------------------------------------------------
__global__ __launch_bounds__(256) void qkv_kernel(
    const float* __restrict__ x,
    const float* __restrict__ Wq,
    const float* __restrict__ Wk,
    const float* __restrict__ Wv)
{
    __shared__ float xs[128 * 20];      // 128 rows x 16 k, stride 20
    __shared__ float ws[16 * 196];      // 16 k x 192 cols, stride 196

    const int tid = threadIdx.x;
    const int ti  = tid >> 4;           // 0..15 -> rows 8*ti..
    const int tj  = tid & 15;           // 0..15 -> 4-col quad per matrix
    const int r0  = ti * 8;
    const int row0 = blockIdx.x * 128;

    float acc[3][8][4];
    #pragma unroll
    for (int m = 0; m < 3; m++)
        #pragma unroll
        for (int i = 0; i < 8; i++)
            #pragma unroll
            for (int c = 0; c < 4; c++)
                acc[m][i][c] = 0.0f;

    const int xr = tid >> 2;            // 0..63
    const int xq = (tid & 3) * 4;
    const int wk = tid >> 4;            // 0..15
    const int wc = (tid & 15) * 4;      // 0..60

    for (int k0 = 0; k0 < DD; k0 += 16) {
        __syncthreads();
        {
            float4 v0 = *(const float4*)&x[(size_t)(row0 + xr) * DD + k0 + xq];
            *(float4*)&xs[xr * 20 + xq] = v0;
            float4 v1 = *(const float4*)&x[(size_t)(row0 + xr + 64) * DD + k0 + xq];
            *(float4*)&xs[(xr + 64) * 20 + xq] = v1;
        }
        {
            *(float4*)&ws[wk * 196 +   0 + wc] = *(const float4*)&Wq[(size_t)(k0 + wk) * HH + wc];
            *(float4*)&ws[wk * 196 +  64 + wc] = *(const float4*)&Wk[(size_t)(k0 + wk) * HH + wc];
            *(float4*)&ws[wk * 196 + 128 + wc] = *(const float4*)&Wv[(size_t)(k0 + wk) * HH + wc];
        }
        __syncthreads();

        #pragma unroll
        for (int kq = 0; kq < 4; kq++) {
            float4 xv[8];
            #pragma unroll
            for (int ri = 0; ri < 8; ri++)
                xv[ri] = *(const float4*)&xs[(r0 + ri) * 20 + kq * 4];
            #pragma unroll
            for (int k2 = 0; k2 < 4; k2++) {
                const int kk = kq * 4 + k2;
                float4 wv[3];
                #pragma unroll
                for (int m = 0; m < 3; m++)
                    wv[m] = *(const float4*)&ws[kk * 196 + m * 64 + tj * 4];
                #pragma unroll
                for (int ri = 0; ri < 8; ri++) {
                    float xs1 = (k2 == 0) ? xv[ri].x : (k2 == 1) ? xv[ri].y
                              : (k2 == 2) ? xv[ri].z : xv[ri].w;
                    #pragma unroll
                    for (int m = 0; m < 3; m++) {
                        acc[m][ri][0] = fmaf(xs1, wv[m].x, acc[m][ri][0]);
                        acc[m][ri][1] = fmaf(xs1, wv[m].y, acc[m][ri][1]);
                        acc[m][ri][2] = fmaf(xs1, wv[m].z, acc[m][ri][2]);
                        acc[m][ri][3] = fmaf(xs1, wv[m].w, acc[m][ri][3]);
                    }
                }
            }
        }
    }

    #pragma unroll
    for (int m = 0; m < 3; m++) {
        float* gout = (m == 0) ? g_Q : ((m == 1) ? g_K : g_V);
        #pragma unroll
        for (int ri = 0; ri < 8; ri++) {
            float4 o = make_float4(acc[m][ri][0], acc[m][ri][1],
                                   acc[m][ri][2], acc[m][ri][3]);
            *(float4*)&gout[(size_t)(row0 + r0 + ri) * HH + tj * 4] = o;
        }
    }
}

// ---------------------------------------------------------------------------
// Kernel 2: causal flash attention, fp32, online softmax.
// BM=64 queries, BN=128 keys per tile, 128 threads (8x16 grid).
// S microtile 8x8 (1.0 B/FMA), PV microtile 8x4 over full j (1.5 B/FMA).
// Dynamic smem: Qs 16K + Ks 32K + Vs 32K + Ps 33K = 113K -> 2 CTAs/SM.
// ---------------------------------------------------------------------------
#define PS_STRIDE 132

__global__ __launch_bounds__(128) void attn_kernel(float* __restrict__ out)
{
    extern __shared__ float sm[];
    float* Qs = sm;                       // 64 x 64
    float* Ks = sm + 64 * 64;             // 128 x 64, quad-swizzled
    float* Vs = sm + 64 * 64 + 128 * 64;  // 128 x 64
    float* Ps = sm + 64 * 64 + 2 * 128 * 64;  // 64 x PS_STRIDE

    const int tid = threadIdx.x;
    const int ti  = tid >> 4;             // 0..7  -> rows 8*ti..
    const int tj  = tid & 15;             // 0..15 -> S cols 8*tj.., O cols 4*tj..
    const int r0  = ti * 8;

    const int b  = blockIdx.y;
    const int qt = gridDim.x - 1 - blockIdx.x;   // heavy blocks first
    const int q0 = qt * 64;
    const size_t base = (size_t)b * TT * HH;

    // Load Q tile (64x64 = 1024 float4, 8 iters x 128 thr), pre-scaled by 1/8.
    #pragma unroll
    for (int i = 0; i < 8; i++) {
        int f   = tid + i * 128;
        int row = f >> 4;
        int q   = f & 15;
        float4 v = *(const float4*)&g_Q[base + (size_t)(q0 + row) * HH + q * 4];
        v.x *= 0.125f; v.y *= 0.125f; v.z *= 0.125f; v.w *= 0.125f;
        *(float4*)&Qs[row * 64 + q * 4] = v;
    }

    float m[8], l[8], O[8][4];
    #pragma unroll
    for (int ri = 0; ri < 8; ri++) {
        m[ri] = -1.0e30f;
        l[ri] = 0.0f;
        O[ri][0] = O[ri][1] = O[ri][2] = O[ri][3] = 0.0f;
    }

    const int lt = (qt >> 1);             // last kv tile (contains diagonal)
    for (int kt = 0; kt <= lt; kt++) {
        const int jbase = kt * 128;
        __syncthreads();                  // previous tile fully consumed
        // stage K, V tiles: 128 rows x 16 quads = 2048 float4 each
        // -> 16 iterations x 128 threads. K quad-swizzled by row>>3.
        #pragma unroll
        for (int i = 0; i < 16; i++) {
            int f   = tid + i * 128;
            int row = f >> 4;
            int q   = f & 15;
            size_t g = base + (size_t)(jbase + row) * HH + q * 4;
            int sq  = q ^ (row >> 3);
            *(float4*)&Ks[row * 64 + sq * 4] = *(const float4*)&g_K[g];
            *(float4*)&Vs[row * 64 + q  * 4] = *(const float4*)&g_V[g];
        }
        __syncthreads();

        // ---- S = Q K^T : 8x8 microtile, k vectorized by 4 ----
        float acc[8][8];
        #pragma unroll
        for (int ri = 0; ri < 8; ri++)
            #pragma unroll
            for (int cj = 0; cj < 8; cj++) acc[ri][cj] = 0.0f;

        #pragma unroll
        for (int kq = 0; kq < 16; kq++) {
            float4 qv[8];
            #pragma unroll
            for (int ri = 0; ri < 8; ri++)
                qv[ri] = *(const float4*)&Qs[(r0 + ri) * 64 + kq * 4];
            #pragma unroll
            for (int half = 0; half < 2; half++) {
                float4 kv[4];
                #pragma unroll
                for (int c = 0; c < 4; c++)
                    kv[c] = *(const float4*)&Ks[(8 * tj + half * 4 + c) * 64 + ((kq ^ tj) << 2)];
                #pragma unroll
                for (int ri = 0; ri < 8; ri++)
                    #pragma unroll
                    for (int c = 0; c < 4; c++) {
                        int cj = half * 4 + c;
                        acc[ri][cj] = fmaf(qv[ri].x, kv[c].x, acc[ri][cj]);
                        acc[ri][cj] = fmaf(qv[ri].y, kv[c].y, acc[ri][cj]);
                        acc[ri][cj] = fmaf(qv[ri].z, kv[c].z, acc[ri][cj]);
                        acc[ri][cj] = fmaf(qv[ri].w, kv[c].w, acc[ri][cj]);
                    }
            }
        }

        const bool diag = (kt == lt);

        // ---- online softmax per owned row (reduce across 16 tj lanes) ----
        #pragma unroll
        for (int ri = 0; ri < 8; ri++) {
            const int rg = q0 + r0 + ri;
            if (diag) {
                #pragma unroll
                for (int cj = 0; cj < 8; cj++)
                    acc[ri][cj] = (jbase + 8 * tj + cj > rg) ? -1.0e30f : acc[ri][cj];
            }
            float mx = acc[ri][0];
            #pragma unroll
            for (int cj = 1; cj < 8; cj++) mx = fmaxf(mx, acc[ri][cj]);
            mx = fmaxf(mx, __shfl_xor_sync(0xffffffffu, mx, 1));
            mx = fmaxf(mx, __shfl_xor_sync(0xffffffffu, mx, 2));
            mx = fmaxf(mx, __shfl_xor_sync(0xffffffffu, mx, 4));
            mx = fmaxf(mx, __shfl_xor_sync(0xffffffffu, mx, 8));

            float newm = fmaxf(m[ri], mx);
            float corr = __expf(m[ri] - newm);

            float ls = 0.0f;
            float p[8];
            #pragma unroll
            for (int cj = 0; cj < 8; cj++) {
                p[cj] = __expf(acc[ri][cj] - newm);
                ls += p[cj];
            }
            *(float4*)&Ps[(r0 + ri) * PS_STRIDE + 8 * tj + 0] =
                make_float4(p[0], p[1], p[2], p[3]);
            *(float4*)&Ps[(r0 + ri) * PS_STRIDE + 8 * tj + 4] =
                make_float4(p[4], p[5], p[6], p[7]);

            ls += __shfl_xor_sync(0xffffffffu, ls, 1);
            ls += __shfl_xor_sync(0xffffffffu, ls, 2);
            ls += __shfl_xor_sync(0xffffffffu, ls, 4);
            ls += __shfl_xor_sync(0xffffffffu, ls, 8);

            l[ri] = l[ri] * corr + ls;
            m[ri] = newm;
            O[ri][0] *= corr; O[ri][1] *= corr;
            O[ri][2] *= corr; O[ri][3] *= corr;
        }
        __syncthreads();   // Ps visible across tj

        // ---- O += P @ V  (8 rows x 4 h-cols per thread, j over 128) ----
        #pragma unroll 4
        for (int j4 = 0; j4 < 128; j4 += 4) {
            float4 pv[8];
            #pragma unroll
            for (int ri = 0; ri < 8; ri++)
                pv[ri] = *(const float4*)&Ps[(r0 + ri) * PS_STRIDE + j4];
            float4 vv[4];
            #pragma unroll
            for (int jj = 0; jj < 4; jj++)
                vv[jj] = *(const float4*)&Vs[(j4 + jj) * 64 + tj * 4];
            #pragma unroll
            for (int ri = 0; ri < 8; ri++) {
                O[ri][0] = fmaf(pv[ri].x, vv[0].x, O[ri][0]);
                O[ri][1] = fmaf(pv[ri].x, vv[0].y, O[ri][1]);
                O[ri][2] = fmaf(pv[ri].x, vv[0].z, O[ri][2]);
                O[ri][3] = fmaf(pv[ri].x, vv[0].w, O[ri][3]);
                O[ri][0] = fmaf(pv[ri].y, vv[1].x, O[ri][0]);
                O[ri][1] = fmaf(pv[ri].y, vv[1].y, O[ri][1]);
                O[ri][2] = fmaf(pv[ri].y, vv[1].z, O[ri][2]);
                O[ri][3] = fmaf(pv[ri].y, vv[1].w, O[ri][3]);
                O[ri][0] = fmaf(pv[ri].z, vv[2].x, O[ri][0]);
                O[ri][1] = fmaf(pv[ri].z, vv[2].y, O[ri][1]);
                O[ri][2] = fmaf(pv[ri].z, vv[2].z, O[ri][2]);
                O[ri][3] = fmaf(pv[ri].z, vv[2].w, O[ri][3]);
                O[ri][0] = fmaf(pv[ri].w, vv[3].x, O[ri][0]);
                O[ri][1] = fmaf(pv[ri].w, vv[3].y, O[ri][1]);
                O[ri][2] = fmaf(pv[ri].w, vv[3].z, O[ri][2]);
                O[ri][3] = fmaf(pv[ri].w, vv[3].w, O[ri][3]);
            }
        }
    }

    // epilogue: normalize and store
    #pragma unroll
    for (int ri = 0; ri < 8; ri++) {
        float inv = 1.0f / l[ri];
        float4 o = make_float4(O[ri][0] * inv, O[ri][1] * inv,
                               O[ri][2] * inv, O[ri][3] * inv);
        *(float4*)&out[base + (size_t)(q0 + r0 + ri) * HH + tj * 4] = o;
    }
}

// ---------------------------------------------------------------------------
extern "C" void kernel_launch(void* const* d_in, const int* in_sizes, int n_in,
                              void* d_out, int out_size)
{
    const float* x  = (const float*)d_in[0];
    const float* Wq = (const float*)d_in[1];
    const float* Wk = (const float*)d_in[2];
    const float* Wv = (const float*)d_in[3];
    float* out = (float*)d_out;

    const int attn_smem = (64 * 64 + 2 * 128 * 64 + 64 * PS_STRIDE) * sizeof(float);
    cudaFuncSetAttribute(attn_kernel, cudaFuncAttributeMaxDynamicSharedMemorySize,
                         attn_smem);

    qkv_kernel<<<BT / 128, 256>>>(x, Wq, Wk, Wv);
    attn_kernel<<<dim3(TT / 64, BB), 128, attn_smem>>>(out);
}

// round 4
// speedup vs baseline: 1.8069x; 1.8069x over previous
#include <cuda_runtime.h>
#include <cuda_bf16.h>
#include <cstdint>

#define BB 4
#define TT 4096
#define DD 768
#define HH 64
#define BT (BB*TT)

// Scratch for projected Q, K, V (fp32).
__device__ float g_Q[BT * HH];
__device__ float g_K[BT * HH];
__device__ float g_V[BT * HH];

// ---------------------------------------------------------------------------
// tf32 helpers
// ---------------------------------------------------------------------------
__device__ __forceinline__ uint32_t f2tf(float f) {
    uint32_t u;
    asm("cvt.rna.tf32.f32 %0, %1;" : "=r"(u) : "f"(f));
    return u;
}

__device__ __forceinline__ void mma_tf32(float d[4], const uint32_t a[4],
                                         uint32_t b0, uint32_t b1) {
    asm volatile(
        "mma.sync.aligned.m16n8k8.row.col.f32.tf32.tf32.f32 "
        "{%0,%1,%2,%3}, {%4,%5,%6,%7}, {%8,%9}, {%0,%1,%2,%3};"
        : "+f"(d[0]), "+f"(d[1]), "+f"(d[2]), "+f"(d[3])
        : "r"(a[0]), "r"(a[1]), "r"(a[2]), "r"(a[3]), "r"(b0), "r"(b1));
}

// ---------------------------------------------------------------------------
// Kernel 1: fused QKV projection (unchanged from R3 — known correct, ~peak).
// ---------------------------------------------------------------------------
__global__ __launch_bounds__(256) void qkv_kernel(
    const float* __restrict__ x,
    const float* __restrict__ Wq,
    const float* __restrict__ Wk,
    const float* __restrict__ Wv)
{
    __shared__ float xs[128 * 20];
    __shared__ float ws[16 * 196];

    const int tid = threadIdx.x;
    const int ti  = tid >> 4;
    const int tj  = tid & 15;
    const int r0  = ti * 8;
    const int row0 = blockIdx.x * 128;

    float acc[3][8][4];
    #pragma unroll
    for (int m = 0; m < 3; m++)
        #pragma unroll
        for (int i = 0; i < 8; i++)
            #pragma unroll
            for (int c = 0; c < 4; c++)
                acc[m][i][c] = 0.0f;

    const int xr = tid >> 2;
    const int xq = (tid & 3) * 4;
    const int wk = tid >> 4;
    const int wc = (tid & 15) * 4;

    for (int k0 = 0; k0 < DD; k0 += 16) {
        __syncthreads();
        {
            float4 v0 = *(const float4*)&x[(size_t)(row0 + xr) * DD + k0 + xq];
            *(float4*)&xs[xr * 20 + xq] = v0;
            float4 v1 = *(const float4*)&x[(size_t)(row0 + xr + 64) * DD + k0 + xq];
            *(float4*)&xs[(xr + 64) * 20 + xq] = v1;
        }
        {
            *(float4*)&ws[wk * 196 +   0 + wc] = *(const float4*)&Wq[(size_t)(k0 + wk) * HH + wc];
            *(float4*)&ws[wk * 196 +  64 + wc] = *(const float4*)&Wk[(size_t)(k0 + wk) * HH + wc];
            *(float4*)&ws[wk * 196 + 128 + wc] = *(const float4*)&Wv[(size_t)(k0 + wk) * HH + wc];
        }
        __syncthreads();

        #pragma unroll
        for (int kq = 0; kq < 4; kq++) {
            float4 xv[8];
            #pragma unroll
            for (int ri = 0; ri < 8; ri++)
                xv[ri] = *(const float4*)&xs[(r0 + ri) * 20 + kq * 4];
            #pragma unroll
            for (int k2 = 0; k2 < 4; k2++) {
                const int kk = kq * 4 + k2;
                float4 wv[3];
                #pragma unroll
                for (int m = 0; m < 3; m++)
                    wv[m] = *(const float4*)&ws[kk * 196 + m * 64 + tj * 4];
                #pragma unroll
                for (int ri = 0; ri < 8; ri++) {
                    float xs1 = (k2 == 0) ? xv[ri].x : (k2 == 1) ? xv[ri].y
                              : (k2 == 2) ? xv[ri].z : xv[ri].w;
                    #pragma unroll
                    for (int m = 0; m < 3; m++) {
                        acc[m][ri][0] = fmaf(xs1, wv[m].x, acc[m][ri][0]);
                        acc[m][ri][1] = fmaf(xs1, wv[m].y, acc[m][ri][1]);
                        acc[m][ri][2] = fmaf(xs1, wv[m].z, acc[m][ri][2]);
                        acc[m][ri][3] = fmaf(xs1, wv[m].w, acc[m][ri][3]);
                    }
                }
            }
        }
    }

    #pragma unroll
    for (int m = 0; m < 3; m++) {
        float* gout = (m == 0) ? g_Q : ((m == 1) ? g_K : g_V);
        #pragma unroll
        for (int ri = 0; ri < 8; ri++) {
            float4 o = make_float4(acc[m][ri][0], acc[m][ri][1],
                                   acc[m][ri][2], acc[m][ri][3]);
            *(float4*)&gout[(size_t)(row0 + r0 + ri) * HH + tj * 4] = o;
        }
    }
}

// ---------------------------------------------------------------------------
// Kernel 2: causal flash attention on tensor cores (mma.sync tf32).
// BM=64 (4 warps x m16), BN=64, head=64.
// K/V staged in fragment-native smem layout (frag stride 66 -> LDS.64
// conflict-free). P round-trips via stride-68 smem (A-frag LDS bank = lane).
// Work-balanced rank mapping: colocated CTAs (bid, bid+148) sum ~const work.
// ---------------------------------------------------------------------------
#define FSTR 66
#define PSTR 68

__global__ __launch_bounds__(128) void attn_kernel(float* __restrict__ out)
{
    extern __shared__ float sm[];
    float* Ksf = sm;                    // 64 frags x FSTR
    float* Vsf = sm + 64 * FSTR;        // 64 frags x FSTR
    float* Ps  = sm + 2 * 64 * FSTR;    // 64 rows x PSTR

    const int tid = threadIdx.x;
    const int w   = tid >> 5;           // warp 0..3 -> rows w*16..
    const int l   = tid & 31;
    const int r   = l >> 2;             // group id 0..7
    const int c   = l & 3;              // thread-in-group

    // balanced (b, qt) assignment
    const int bid = blockIdx.x;
    const int rk  = (bid < 148) ? bid : (403 - bid);
    const int b   = rk & 3;
    const int qt  = 63 - (rk >> 2);
    const int q0  = qt * 64;
    const size_t base = (size_t)b * TT * HH;

    const int rowg  = q0 + w * 16 + r;
    const int rowg8 = rowg + 8;

    // --- Q fragments in registers for the whole CTA (scaled, rna-rounded) ---
    uint32_t qf[8][4];
    #pragma unroll
    for (int kb = 0; kb < 8; kb++) {
        qf[kb][0] = f2tf(0.125f * g_Q[base + (size_t)rowg  * HH + kb * 8 + c]);
        qf[kb][1] = f2tf(0.125f * g_Q[base + (size_t)rowg8 * HH + kb * 8 + c]);
        qf[kb][2] = f2tf(0.125f * g_Q[base + (size_t)rowg  * HH + kb * 8 + c + 4]);
        qf[kb][3] = f2tf(0.125f * g_Q[base + (size_t)rowg8 * HH + kb * 8 + c + 4]);
    }

    float o[8][4];
    #pragma unroll
    for (int hb = 0; hb < 8; hb++)
        o[hb][0] = o[hb][1] = o[hb][2] = o[hb][3] = 0.0f;
    float mR = -1.0e30f, mR8 = -1.0e30f, lR = 0.0f, lR8 = 0.0f;

    for (int kt = 0; kt <= qt; kt++) {
        const int jbase = kt * 64;
        __syncthreads();   // previous tile's Ksf/Vsf fully consumed

        // ---- stage K, V into fragment-native layout ----
        #pragma unroll
        for (int i = 0; i < 8; i++) {
            const int f  = tid + i * 128;       // 0..1023
            const int j  = f >> 4;              // key row 0..63
            const int h0 = (f & 15) << 2;       // head col, 4-aligned
            const size_t g = base + (size_t)(jbase + j) * HH + h0;
            float4 k4 = *(const float4*)&g_K[g];
            float4 v4 = *(const float4*)&g_V[g];

            // K: frag (kb = h0/8, nb = j/8), slot = (h0%8)/4, lane = (j%8)*4 + e
            {
                const int frK  = ((h0 >> 3) << 3) + (j >> 3);
                const int slot = (h0 >> 2) & 1;
                const int lb   = (j & 7) << 2;
                float* p = &Ksf[frK * FSTR + slot];
                p[(lb + 0) * 2] = __uint_as_float(f2tf(k4.x));
                p[(lb + 1) * 2] = __uint_as_float(f2tf(k4.y));
                p[(lb + 2) * 2] = __uint_as_float(f2tf(k4.z));
                p[(lb + 3) * 2] = __uint_as_float(f2tf(k4.w));
            }
            // V: frag (kb = j/8, hb = h0/8), slot = (j%8)/4, lane = ((h0+e)%8)*4 + j%4
            {
                const int frV  = ((j >> 3) << 3) + (h0 >> 3);
                const int slot = (j >> 2) & 1;
                const int h7   = h0 & 7;        // 0 or 4
                const int j3   = j & 3;
                float* p = &Vsf[frV * FSTR + slot];
                p[((h7 + 0) * 4 + j3) * 2] = v4.x;
                p[((h7 + 1) * 4 + j3) * 2] = v4.y;
                p[((h7 + 2) * 4 + j3) * 2] = v4.z;
                p[((h7 + 3) * 4 + j3) * 2] = v4.w;
            }
        }
        __syncthreads();

        // ---- S = Q K^T ----
        float s[8][4];
        #pragma unroll
        for (int nb = 0; nb < 8; nb++)
            s[nb][0] = s[nb][1] = s[nb][2] = s[nb][3] = 0.0f;

        #pragma unroll
        for (int nb = 0; nb < 8; nb++) {
            #pragma unroll
            for (int kb = 0; kb < 8; kb++) {
                float2 t = *(const float2*)&Ksf[(kb * 8 + nb) * FSTR + l * 2];
                mma_tf32(s[nb], qf[kb], __float_as_uint(t.x), __float_as_uint(t.y));
            }
        }

        // ---- causal mask (diagonal tile only) ----
        if (kt == qt) {
            #pragma unroll
            for (int nb = 0; nb < 8; nb++) {
                const int col = jbase + nb * 8 + 2 * c;
                if (col     > rowg ) s[nb][0] = -1.0e30f;
                if (col + 1 > rowg ) s[nb][1] = -1.0e30f;
                if (col     > rowg8) s[nb][2] = -1.0e30f;
                if (col + 1 > rowg8) s[nb][3] = -1.0e30f;
            }
        }

        // ---- online softmax (rows rowg and rowg8, quad-reduced) ----
        float mx0 = -1.0e30f, mx1 = -1.0e30f;
        #pragma unroll
        for (int nb = 0; nb < 8; nb++) {
            mx0 = fmaxf(mx0, fmaxf(s[nb][0], s[nb][1]));
            mx1 = fmaxf(mx1, fmaxf(s[nb][2], s[nb][3]));
        }
        mx0 = fmaxf(mx0, __shfl_xor_sync(0xffffffffu, mx0, 1));
        mx0 = fmaxf(mx0, __shfl_xor_sync(0xffffffffu, mx0, 2));
        mx1 = fmaxf(mx1, __shfl_xor_sync(0xffffffffu, mx1, 1));
        mx1 = fmaxf(mx1, __shfl_xor_sync(0xffffffffu, mx1, 2));

        const float nm0 = fmaxf(mR, mx0);
        const float nm1 = fmaxf(mR8, mx1);
        const float corr0 = __expf(mR - nm0);
        const float corr1 = __expf(mR8 - nm1);

        float sum0 = 0.0f, sum1 = 0.0f;
        #pragma unroll
        for (int nb = 0; nb < 8; nb++) {
            s[nb][0] = __expf(s[nb][0] - nm0);
            s[nb][1] = __expf(s[nb][1] - nm0);
            s[nb][2] = __expf(s[nb][2] - nm1);
            s[nb][3] = __expf(s[nb][3] - nm1);
            sum0 += s[nb][0] + s[nb][1];
            sum1 += s[nb][2] + s[nb][3];
            *(float2*)&Ps[(w * 16 + r    ) * PSTR + nb * 8 + 2 * c] =
                make_float2(s[nb][0], s[nb][1]);
            *(float2*)&Ps[(w * 16 + r + 8) * PSTR + nb * 8 + 2 * c] =
                make_float2(s[nb][2], s[nb][3]);
        }
        sum0 += __shfl_xor_sync(0xffffffffu, sum0, 1);
        sum0 += __shfl_xor_sync(0xffffffffu, sum0, 2);
        sum1 += __shfl_xor_sync(0xffffffffu, sum1, 1);
        sum1 += __shfl_xor_sync(0xffffffffu, sum1, 2);

        lR  = lR  * corr0 + sum0;  mR  = nm0;
        lR8 = lR8 * corr1 + sum1;  mR8 = nm1;
        #pragma unroll
        for (int hb = 0; hb < 8; hb++) {
            o[hb][0] *= corr0; o[hb][1] *= corr0;
            o[hb][2] *= corr1; o[hb][3] *= corr1;
        }
        __syncwarp();   // cross-lane Ps visibility (warp-private rows)

        // ---- O += P @ V ----
        #pragma unroll
        for (int kb = 0; kb < 8; kb++) {
            uint32_t a[4];
            a[0] = __float_as_uint(Ps[(w * 16 + r    ) * PSTR + kb * 8 + c]);
            a[1] = __float_as_uint(Ps[(w * 16 + r + 8) * PSTR + kb * 8 + c]);
            a[2] = __float_as_uint(Ps[(w * 16 + r    ) * PSTR + kb * 8 + c + 4]);
            a[3] = __float_as_uint(Ps[(w * 16 + r + 8) * PSTR + kb * 8 + c + 4]);
            #pragma unroll
            for (int hb = 0; hb < 8; hb++) {
                float2 t = *(const float2*)&Vsf[(kb * 8 + hb) * FSTR + l * 2];
                mma_tf32(o[hb], a, __float_as_uint(t.x), __float_as_uint(t.y));
            }
        }
    }

    // ---- epilogue: normalize, store ----
    const float inv0 = 1.0f / lR;
    const float inv1 = 1.0f / lR8;
    #pragma unroll
    for (int hb = 0; hb < 8; hb++) {
        *(float2*)&out[base + (size_t)rowg  * HH + hb * 8 + 2 * c] =
            make_float2(o[hb][0] * inv0, o[hb][1] * inv0);
        *(float2*)&out[base + (size_t)rowg8 * HH + hb * 8 + 2 * c] =
            make_float2(o[hb][2] * inv1, o[hb][3] * inv1);
    }
}

// ---------------------------------------------------------------------------
extern "C" void kernel_launch(void* const* d_in, const int* in_sizes, int n_in,
                              void* d_out, int out_size)
{
    const float* x  = (const float*)d_in[0];
    const float* Wq = (const float*)d_in[1];
    const float* Wk = (const float*)d_in[2];
    const float* Wv = (const float*)d_in[3];
    float* out = (float*)d_out;

    const int attn_smem = (2 * 64 * FSTR + 64 * PSTR) * sizeof(float);  // 51200 B
    cudaFuncSetAttribute(attn_kernel, cudaFuncAttributeMaxDynamicSharedMemorySize,
                         attn_smem);

    qkv_kernel<<<BT / 128, 256>>>(x, Wq, Wk, Wv);
    attn_kernel<<<BB * (TT / 64), 128, attn_smem>>>(out);
}

// round 5
// speedup vs baseline: 2.2906x; 1.2677x over previous
#include <cuda_runtime.h>
#include <cuda_bf16.h>
#include <cstdint>

#define BB 4
#define TT 4096
#define DD 768
#define HH 64
#define BT (BB*TT)

// Scratch
__device__ float  g_Q[BT * HH];
__device__ float  g_K[BT * HH];
__device__ float  g_V[BT * HH];
__device__ float2 g_Wsp[DD * 192];        // W (Q|K|V) split into (tf32 hi, tf32 lo)
__device__ float  g_pO[2 * BT * HH];      // split-kv partial O (unnormalized)
__device__ float  g_pm[2 * BT];           // partial running max
__device__ float  g_pl[2 * BT];           // partial denom

// ---------------------------------------------------------------------------
// tf32 helpers
// ---------------------------------------------------------------------------
__device__ __forceinline__ uint32_t f2tf(float f) {
    uint32_t u;
    asm("cvt.rna.tf32.f32 %0, %1;" : "=r"(u) : "f"(f));
    return u;
}
__device__ __forceinline__ float tf32f(float f) {
    return __uint_as_float(f2tf(f));
}

__device__ __forceinline__ void mma_tf32(float d[4], const uint32_t a[4],
                                         uint32_t b0, uint32_t b1) {
    asm volatile(
        "mma.sync.aligned.m16n8k8.row.col.f32.tf32.tf32.f32 "
        "{%0,%1,%2,%3}, {%4,%5,%6,%7}, {%8,%9}, {%0,%1,%2,%3};"
        : "+f"(d[0]), "+f"(d[1]), "+f"(d[2]), "+f"(d[3])
        : "r"(a[0]), "r"(a[1]), "r"(a[2]), "r"(a[3]), "r"(b0), "r"(b1));
}

// ---------------------------------------------------------------------------
// Kernel 0: split W = [Wq|Wk|Wv] into (hi, lo) tf32 pair. 147456 elems.
// ---------------------------------------------------------------------------
__global__ __launch_bounds__(256) void prep_w(
    const float* __restrict__ Wq, const float* __restrict__ Wk,
    const float* __restrict__ Wv)
{
    int i = blockIdx.x * 256 + threadIdx.x;
    if (i >= DD * 192) return;
    int k = i / 192, n = i % 192;
    float v = (n < 64) ? Wq[k * 64 + n]
            : (n < 128) ? Wk[k * 64 + n - 64]
            : Wv[k * 64 + n - 128];
    float hi = tf32f(v);
    float lo = tf32f(v - hi);
    g_Wsp[i] = make_float2(hi, lo);
}

// ---------------------------------------------------------------------------
// Kernel 1: QKV projection on tensor cores, 3-term tf32 split (~fp32 exact).
// C[16384 x 192] = x @ W.  CTA: BM=128 rows, BN=96 cols, 256 thr (8 warps).
// Warp (mg = w>>1, ng = w&1): rows mg*32..+32 (2 m16 tiles), nb cols ng*6..+6.
// ---------------------------------------------------------------------------
__global__ __launch_bounds__(256) void qkv_mma(const float* __restrict__ x)
{
    __shared__ float  xs[128 * 36];        // raw x tile, stride 36 (bank-clean)
    __shared__ float4 wf[4 * 12 * 33];     // frag-major W: [kb*12+nb][lane]

    const int tid = threadIdx.x;
    const int w   = tid >> 5;
    const int l   = tid & 31;
    const int mg  = w >> 1;                // 0..3
    const int ng  = w & 1;                 // 0..1
    const int row0 = (blockIdx.x >> 1) * 128;
    const int n0   = (blockIdx.x & 1) * 96;

    float acc[2][6][4];
    #pragma unroll
    for (int mt = 0; mt < 2; mt++)
        #pragma unroll
        for (int nb = 0; nb < 6; nb++)
            acc[mt][nb][0] = acc[mt][nb][1] = acc[mt][nb][2] = acc[mt][nb][3] = 0.0f;

    for (int k0 = 0; k0 < DD; k0 += 32) {
        __syncthreads();
        // stage x: 128 x 32 floats = 1024 float4, 4 per thread (coalesced)
        #pragma unroll
        for (int t = 0; t < 4; t++) {
            int f  = tid + t * 256;
            int r  = f >> 3;
            int c4 = (f & 7) * 4;
            float4 v = *(const float4*)&x[(size_t)(row0 + r) * DD + k0 + c4];
            *(float4*)&xs[r * 36 + c4] = v;
        }
        // stage W frags: 32 k x 96 n (hi,lo), 12 elems per thread
        #pragma unroll
        for (int t = 0; t < 12; t++) {
            int i  = tid + t * 256;         // 0..3071
            int kk = i / 96;
            int nn = i % 96;
            float2 hv = g_Wsp[(size_t)(k0 + kk) * 192 + n0 + nn];
            int kb   = kk >> 3, kr = kk & 7;
            int slot = kr >> 2;
            int nb   = nn >> 3;
            int lane = ((nn & 7) << 2) | (kr & 3);
            float* p = (float*)&wf[(kb * 12 + nb) * 33 + lane];
            p[slot]     = hv.x;             // hi: b0 / b1
            p[2 + slot] = hv.y;             // lo: b0 / b1
        }
        __syncthreads();

        #pragma unroll
        for (int kb = 0; kb < 4; kb++) {
            // A fragments for 2 m-tiles, split hi/lo
            uint32_t ahi[2][4], alo[2][4];
            #pragma unroll
            for (int mt = 0; mt < 2; mt++) {
                const int rA = mg * 32 + mt * 16 + (l >> 2);
                const int cA = kb * 8 + (l & 3);
                float a0 = xs[rA * 36 + cA];
                float a1 = xs[(rA + 8) * 36 + cA];
                float a2 = xs[rA * 36 + cA + 4];
                float a3 = xs[(rA + 8) * 36 + cA + 4];
                ahi[mt][0] = f2tf(a0); alo[mt][0] = f2tf(a0 - __uint_as_float(ahi[mt][0]));
                ahi[mt][1] = f2tf(a1); alo[mt][1] = f2tf(a1 - __uint_as_float(ahi[mt][1]));
                ahi[mt][2] = f2tf(a2); alo[mt][2] = f2tf(a2 - __uint_as_float(ahi[mt][2]));
                ahi[mt][3] = f2tf(a3); alo[mt][3] = f2tf(a3 - __uint_as_float(ahi[mt][3]));
            }
            #pragma unroll
            for (int nb = 0; nb < 6; nb++) {
                float4 q = wf[(kb * 12 + ng * 6 + nb) * 33 + l];
                uint32_t bh0 = __float_as_uint(q.x), bh1 = __float_as_uint(q.y);
                uint32_t bl0 = __float_as_uint(q.z), bl1 = __float_as_uint(q.w);
                #pragma unroll
                for (int mt = 0; mt < 2; mt++) {
                    mma_tf32(acc[mt][nb], ahi[mt], bh0, bh1);
                    mma_tf32(acc[mt][nb], ahi[mt], bl0, bl1);
                    mma_tf32(acc[mt][nb], alo[mt], bh0, bh1);
                }
            }
        }
    }

    // store to g_Q / g_K / g_V
    #pragma unroll
    for (int mt = 0; mt < 2; mt++) {
        #pragma unroll
        for (int nb = 0; nb < 6; nb++) {
            const int rowa  = row0 + mg * 32 + mt * 16 + (l >> 2);
            const int nglob = n0 + ng * 48 + nb * 8 + (l & 3) * 2;
            const int mat   = nglob >> 6;
            const int col   = nglob & 63;
            float* g = (mat == 0) ? g_Q : (mat == 1) ? g_K : g_V;
            *(float2*)&g[(size_t)rowa * HH + col] =
                make_float2(acc[mt][nb][0], acc[mt][nb][1]);
            *(float2*)&g[(size_t)(rowa + 8) * HH + col] =
                make_float2(acc[mt][nb][2], acc[mt][nb][3]);
        }
    }
}

// ---------------------------------------------------------------------------
// Kernel 2: causal flash attention, tensor cores, SPLIT-KV (2 splits).
// grid 512: bid -> qt = 63-(bid>>3) (heavy first), b = (bid>>1)&3, s = bid&1.
// Split s covers kv tiles [0,h) or [h,qt+1), h = (qt+2)>>1.
// Writes unnormalized partial (O, m, l) to scratch; combine kernel merges.
// ---------------------------------------------------------------------------
#define FSTR 66
#define PSTR 68

__global__ __launch_bounds__(128) void attn_kernel()
{
    extern __shared__ float sm[];
    float* Ksf = sm;
    float* Vsf = sm + 64 * FSTR;
    float* Ps  = sm + 2 * 64 * FSTR;

    const int tid = threadIdx.x;
    const int w   = tid >> 5;
    const int l   = tid & 31;
    const int r   = l >> 2;
    const int c   = l & 3;

    const int bid = blockIdx.x;
    const int qt  = 63 - (bid >> 3);
    const int b   = (bid >> 1) & 3;
    const int s   = bid & 1;
    const int q0  = qt * 64;
    const size_t base = (size_t)b * TT * HH;

    const int h     = (qt + 2) >> 1;
    const int ktbeg = s ? h : 0;
    const int ktend = s ? (qt + 1) : h;

    const int rowg  = q0 + w * 16 + r;
    const int rowg8 = rowg + 8;

    // Q fragments in registers (scaled by 1/8, tf32-rounded)
    uint32_t qf[8][4];
    #pragma unroll
    for (int kb = 0; kb < 8; kb++) {
        qf[kb][0] = f2tf(0.125f * g_Q[base + (size_t)rowg  * HH + kb * 8 + c]);
        qf[kb][1] = f2tf(0.125f * g_Q[base + (size_t)rowg8 * HH + kb * 8 + c]);
        qf[kb][2] = f2tf(0.125f * g_Q[base + (size_t)rowg  * HH + kb * 8 + c + 4]);
        qf[kb][3] = f2tf(0.125f * g_Q[base + (size_t)rowg8 * HH + kb * 8 + c + 4]);
    }

    float o[8][4];
    #pragma unroll
    for (int hb = 0; hb < 8; hb++)
        o[hb][0] = o[hb][1] = o[hb][2] = o[hb][3] = 0.0f;
    float mR = -1.0e30f, mR8 = -1.0e30f, lR = 0.0f, lR8 = 0.0f;

    for (int kt = ktbeg; kt < ktend; kt++) {
        const int jbase = kt * 64;
        __syncthreads();

        // stage K, V into fragment-native layout
        #pragma unroll
        for (int i = 0; i < 8; i++) {
            const int f  = tid + i * 128;
            const int j  = f >> 4;
            const int h0 = (f & 15) << 2;
            const size_t g = base + (size_t)(jbase + j) * HH + h0;
            float4 k4 = *(const float4*)&g_K[g];
            float4 v4 = *(const float4*)&g_V[g];
            {
                const int frK  = ((h0 >> 3) << 3) + (j >> 3);
                const int slot = (h0 >> 2) & 1;
                const int lb   = (j & 7) << 2;
                float* p = &Ksf[frK * FSTR + slot];
                p[(lb + 0) * 2] = __uint_as_float(f2tf(k4.x));
                p[(lb + 1) * 2] = __uint_as_float(f2tf(k4.y));
                p[(lb + 2) * 2] = __uint_as_float(f2tf(k4.z));
                p[(lb + 3) * 2] = __uint_as_float(f2tf(k4.w));
            }
            {
                const int frV  = ((j >> 3) << 3) + (h0 >> 3);
                const int slot = (j >> 2) & 1;
                const int h7   = h0 & 7;
                const int j3   = j & 3;
                float* p = &Vsf[frV * FSTR + slot];
                p[((h7 + 0) * 4 + j3) * 2] = v4.x;
                p[((h7 + 1) * 4 + j3) * 2] = v4.y;
                p[((h7 + 2) * 4 + j3) * 2] = v4.z;
                p[((h7 + 3) * 4 + j3) * 2] = v4.w;
            }
        }
        __syncthreads();

        // S = Q K^T
        float sS[8][4];
        #pragma unroll
        for (int nb = 0; nb < 8; nb++)
            sS[nb][0] = sS[nb][1] = sS[nb][2] = sS[nb][3] = 0.0f;
        #pragma unroll
        for (int nb = 0; nb < 8; nb++)
            #pragma unroll
            for (int kb = 0; kb < 8; kb++) {
                float2 t = *(const float2*)&Ksf[(kb * 8 + nb) * FSTR + l * 2];
                mma_tf32(sS[nb], qf[kb], __float_as_uint(t.x), __float_as_uint(t.y));
            }

        if (kt == qt) {
            #pragma unroll
            for (int nb = 0; nb < 8; nb++) {
                const int col = jbase + nb * 8 + 2 * c;
                if (col     > rowg ) sS[nb][0] = -1.0e30f;
                if (col + 1 > rowg ) sS[nb][1] = -1.0e30f;
                if (col     > rowg8) sS[nb][2] = -1.0e30f;
                if (col + 1 > rowg8) sS[nb][3] = -1.0e30f;
            }
        }

        // online softmax
        float mx0 = -1.0e30f, mx1 = -1.0e30f;
        #pragma unroll
        for (int nb = 0; nb < 8; nb++) {
            mx0 = fmaxf(mx0, fmaxf(sS[nb][0], sS[nb][1]));
            mx1 = fmaxf(mx1, fmaxf(sS[nb][2], sS[nb][3]));
        }
        mx0 = fmaxf(mx0, __shfl_xor_sync(0xffffffffu, mx0, 1));
        mx0 = fmaxf(mx0, __shfl_xor_sync(0xffffffffu, mx0, 2));
        mx1 = fmaxf(mx1, __shfl_xor_sync(0xffffffffu, mx1, 1));
        mx1 = fmaxf(mx1, __shfl_xor_sync(0xffffffffu, mx1, 2));

        const float nm0 = fmaxf(mR, mx0);
        const float nm1 = fmaxf(mR8, mx1);
        const float corr0 = __expf(mR - nm0);
        const float corr1 = __expf(mR8 - nm1);

        float sum0 = 0.0f, sum1 = 0.0f;
        #pragma unroll
        for (int nb = 0; nb < 8; nb++) {
            sS[nb][0] = __expf(sS[nb][0] - nm0);
            sS[nb][1] = __expf(sS[nb][1] - nm0);
            sS[nb][2] = __expf(sS[nb][2] - nm1);
            sS[nb][3] = __expf(sS[nb][3] - nm1);
            sum0 += sS[nb][0] + sS[nb][1];
            sum1 += sS[nb][2] + sS[nb][3];
            *(float2*)&Ps[(w * 16 + r    ) * PSTR + nb * 8 + 2 * c] =
                make_float2(sS[nb][0], sS[nb][1]);
            *(float2*)&Ps[(w * 16 + r + 8) * PSTR + nb * 8 + 2 * c] =
                make_float2(sS[nb][2], sS[nb][3]);
        }
        sum0 += __shfl_xor_sync(0xffffffffu, sum0, 1);
        sum0 += __shfl_xor_sync(0xffffffffu, sum0, 2);
        sum1 += __shfl_xor_sync(0xffffffffu, sum1, 1);
        sum1 += __shfl_xor_sync(0xffffffffu, sum1, 2);

        lR  = lR  * corr0 + sum0;  mR  = nm0;
        lR8 = lR8 * corr1 + sum1;  mR8 = nm1;
        #pragma unroll
        for (int hb = 0; hb < 8; hb++) {
            o[hb][0] *= corr0; o[hb][1] *= corr0;
            o[hb][2] *= corr1; o[hb][3] *= corr1;
        }
        __syncwarp();

        // O += P @ V
        #pragma unroll
        for (int kb = 0; kb < 8; kb++) {
            uint32_t a[4];
            a[0] = __float_as_uint(Ps[(w * 16 + r    ) * PSTR + kb * 8 + c]);
            a[1] = __float_as_uint(Ps[(w * 16 + r + 8) * PSTR + kb * 8 + c]);
            a[2] = __float_as_uint(Ps[(w * 16 + r    ) * PSTR + kb * 8 + c + 4]);
            a[3] = __float_as_uint(Ps[(w * 16 + r + 8) * PSTR + kb * 8 + c + 4]);
            #pragma unroll
            for (int hb = 0; hb < 8; hb++) {
                float2 t = *(const float2*)&Vsf[(kb * 8 + hb) * FSTR + l * 2];
                mma_tf32(o[hb], a, __float_as_uint(t.x), __float_as_uint(t.y));
            }
        }
    }

    // store partial (unnormalized O, m, l)
    const size_t pr  = (size_t)(s * BB + b) * TT + rowg;   // partial row index
    const size_t pr8 = pr + 8;
    #pragma unroll
    for (int hb = 0; hb < 8; hb++) {
        *(float2*)&g_pO[pr  * HH + hb * 8 + 2 * c] = make_float2(o[hb][0], o[hb][1]);
        *(float2*)&g_pO[pr8 * HH + hb * 8 + 2 * c] = make_float2(o[hb][2], o[hb][3]);
    }
    if (c == 0) {
        g_pm[pr]  = mR;   g_pl[pr]  = lR;
        g_pm[pr8] = mR8;  g_pl[pr8] = lR8;
    }
}

// ---------------------------------------------------------------------------
// Kernel 3: merge the two kv-splits.  out = (O0*a0 + O1*a1)/(l0*a0 + l1*a1).
// ---------------------------------------------------------------------------
__global__ __launch_bounds__(256) void combine_kernel(float* __restrict__ out)
{
    const int gid  = blockIdx.x * 256 + threadIdx.x;   // BT*HH/4 threads
    const int rowg = gid >> 4;                         // global row in [0, BT)
    const int col  = (gid & 15) * 4;

    float m0 = g_pm[rowg],      l0 = g_pl[rowg];
    float m1 = g_pm[BT + rowg], l1 = g_pl[BT + rowg];
    float M  = fmaxf(m0, m1);
    float a0 = __expf(m0 - M);
    float a1 = __expf(m1 - M);
    float inv = 1.0f / (l0 * a0 + l1 * a1);

    float4 O0 = *(const float4*)&g_pO[(size_t)rowg * HH + col];
    float4 O1 = *(const float4*)&g_pO[(size_t)(BT + rowg) * HH + col];
    float4 o;
    o.x = (O0.x * a0 + O1.x * a1) * inv;
    o.y = (O0.y * a0 + O1.y * a1) * inv;
    o.z = (O0.z * a0 + O1.z * a1) * inv;
    o.w = (O0.w * a0 + O1.w * a1) * inv;
    *(float4*)&out[(size_t)rowg * HH + col] = o;
}

// ---------------------------------------------------------------------------
extern "C" void kernel_launch(void* const* d_in, const int* in_sizes, int n_in,
                              void* d_out, int out_size)
{
    const float* x  = (const float*)d_in[0];
    const float* Wq = (const float*)d_in[1];
    const float* Wk = (const float*)d_in[2];
    const float* Wv = (const float*)d_in[3];
    float* out = (float*)d_out;

    const int attn_smem = (2 * 64 * FSTR + 64 * PSTR) * sizeof(float);
    cudaFuncSetAttribute(attn_kernel, cudaFuncAttributeMaxDynamicSharedMemorySize,
                         attn_smem);

    prep_w<<<(DD * 192 + 255) / 256, 256>>>(Wq, Wk, Wv);
    qkv_mma<<<(BT / 128) * 2, 256>>>(x);
    attn_kernel<<<512, 128, attn_smem>>>();
    combine_kernel<<<(BT * HH / 4) / 256, 256>>>(out);
}

// round 6
// speedup vs baseline: 2.7882x; 1.2173x over previous
#include <cuda_runtime.h>
#include <cuda_bf16.h>
#include <cstdint>

#define BB 4
#define TT 4096
#define DD 768
#define HH 64
#define BT (BB*TT)

// Scratch
__device__ float  g_Q[BT * HH];
__device__ float  g_K[BT * HH];
__device__ float  g_V[BT * HH];
__device__ float2 g_Wsp[DD * 192];        // W (Q|K|V) split into (tf32 hi, tf32 lo)
__device__ float  g_pO[2 * BT * HH];      // split-kv partial O (unnormalized)
__device__ float  g_pm[2 * BT];           // partial running max
__device__ float  g_pl[2 * BT];           // partial denom

// ---------------------------------------------------------------------------
// tf32 helpers
// ---------------------------------------------------------------------------
__device__ __forceinline__ uint32_t f2tf(float f) {
    uint32_t u;
    asm("cvt.rna.tf32.f32 %0, %1;" : "=r"(u) : "f"(f));
    return u;
}
__device__ __forceinline__ float tf32f(float f) {
    return __uint_as_float(f2tf(f));
}

__device__ __forceinline__ void mma_tf32(float d[4], const uint32_t a[4],
                                         uint32_t b0, uint32_t b1) {
    asm volatile(
        "mma.sync.aligned.m16n8k8.row.col.f32.tf32.tf32.f32 "
        "{%0,%1,%2,%3}, {%4,%5,%6,%7}, {%8,%9}, {%0,%1,%2,%3};"
        : "+f"(d[0]), "+f"(d[1]), "+f"(d[2]), "+f"(d[3])
        : "r"(a[0]), "r"(a[1]), "r"(a[2]), "r"(a[3]), "r"(b0), "r"(b1));
}

// ---------------------------------------------------------------------------
// Kernel 0: split W = [Wq|Wk|Wv] into (hi, lo) tf32 pair.
// ---------------------------------------------------------------------------
__global__ __launch_bounds__(256) void prep_w(
    const float* __restrict__ Wq, const float* __restrict__ Wk,
    const float* __restrict__ Wv)
{
    int i = blockIdx.x * 256 + threadIdx.x;
    if (i >= DD * 192) return;
    int k = i / 192, n = i % 192;
    float v = (n < 64) ? Wq[k * 64 + n]
            : (n < 128) ? Wk[k * 64 + n - 64]
            : Wv[k * 64 + n - 128];
    float hi = tf32f(v);
    float lo = tf32f(v - hi);
    g_Wsp[i] = make_float2(hi, lo);
}

// ---------------------------------------------------------------------------
// Kernel 1: QKV projection, tensor cores, 3-term tf32 split, SW-PIPELINED:
// next k-tile's global loads are issued before the current tile's MMAs.
// ---------------------------------------------------------------------------
__global__ __launch_bounds__(256) void qkv_mma(const float* __restrict__ x)
{
    __shared__ float  xs[128 * 36];
    __shared__ float4 wf[4 * 12 * 33];

    const int tid = threadIdx.x;
    const int w   = tid >> 5;
    const int l   = tid & 31;
    const int mg  = w >> 1;
    const int ng  = w & 1;
    const int row0 = (blockIdx.x >> 1) * 128;
    const int n0   = (blockIdx.x & 1) * 96;

    float acc[2][6][4];
    #pragma unroll
    for (int mt = 0; mt < 2; mt++)
        #pragma unroll
        for (int nb = 0; nb < 6; nb++)
            acc[mt][nb][0] = acc[mt][nb][1] = acc[mt][nb][2] = acc[mt][nb][3] = 0.0f;

    // prefetch registers
    float4 px[4];
    float2 pw[12];

    // prologue: load k0 = 0
    #pragma unroll
    for (int t = 0; t < 4; t++) {
        int f  = tid + t * 256;
        int r  = f >> 3;
        int c4 = (f & 7) * 4;
        px[t] = *(const float4*)&x[(size_t)(row0 + r) * DD + c4];
    }
    #pragma unroll
    for (int t = 0; t < 12; t++) {
        int i  = tid + t * 256;
        int kk = i / 96;
        int nn = i % 96;
        pw[t] = g_Wsp[(size_t)kk * 192 + n0 + nn];
    }

    for (int k0 = 0; k0 < DD; k0 += 32) {
        // store prefetched tile to smem
        #pragma unroll
        for (int t = 0; t < 4; t++) {
            int f  = tid + t * 256;
            int r  = f >> 3;
            int c4 = (f & 7) * 4;
            *(float4*)&xs[r * 36 + c4] = px[t];
        }
        #pragma unroll
        for (int t = 0; t < 12; t++) {
            int i  = tid + t * 256;
            int kk = i / 96;
            int nn = i % 96;
            int kb   = kk >> 3, kr = kk & 7;
            int slot = kr >> 2;
            int nb   = nn >> 3;
            int lane = ((nn & 7) << 2) | (kr & 3);
            float* p = (float*)&wf[(kb * 12 + nb) * 33 + lane];
            p[slot]     = pw[t].x;
            p[2 + slot] = pw[t].y;
        }
        __syncthreads();

        // prefetch next k-tile (overlaps the MMA work below)
        if (k0 + 32 < DD) {
            #pragma unroll
            for (int t = 0; t < 4; t++) {
                int f  = tid + t * 256;
                int r  = f >> 3;
                int c4 = (f & 7) * 4;
                px[t] = *(const float4*)&x[(size_t)(row0 + r) * DD + k0 + 32 + c4];
            }
            #pragma unroll
            for (int t = 0; t < 12; t++) {
                int i  = tid + t * 256;
                int kk = i / 96;
                int nn = i % 96;
                pw[t] = g_Wsp[(size_t)(k0 + 32 + kk) * 192 + n0 + nn];
            }
        }

        #pragma unroll
        for (int kb = 0; kb < 4; kb++) {
            uint32_t ahi[2][4], alo[2][4];
            #pragma unroll
            for (int mt = 0; mt < 2; mt++) {
                const int rA = mg * 32 + mt * 16 + (l >> 2);
                const int cA = kb * 8 + (l & 3);
                float a0 = xs[rA * 36 + cA];
                float a1 = xs[(rA + 8) * 36 + cA];
                float a2 = xs[rA * 36 + cA + 4];
                float a3 = xs[(rA + 8) * 36 + cA + 4];
                ahi[mt][0] = f2tf(a0); alo[mt][0] = f2tf(a0 - __uint_as_float(ahi[mt][0]));
                ahi[mt][1] = f2tf(a1); alo[mt][1] = f2tf(a1 - __uint_as_float(ahi[mt][1]));
                ahi[mt][2] = f2tf(a2); alo[mt][2] = f2tf(a2 - __uint_as_float(ahi[mt][2]));
                ahi[mt][3] = f2tf(a3); alo[mt][3] = f2tf(a3 - __uint_as_float(ahi[mt][3]));
            }
            #pragma unroll
            for (int nb = 0; nb < 6; nb++) {
                float4 q = wf[(kb * 12 + ng * 6 + nb) * 33 + l];
                uint32_t bh0 = __float_as_uint(q.x), bh1 = __float_as_uint(q.y);
                uint32_t bl0 = __float_as_uint(q.z), bl1 = __float_as_uint(q.w);
                #pragma unroll
                for (int mt = 0; mt < 2; mt++) {
                    mma_tf32(acc[mt][nb], ahi[mt], bh0, bh1);
                    mma_tf32(acc[mt][nb], ahi[mt], bl0, bl1);
                    mma_tf32(acc[mt][nb], alo[mt], bh0, bh1);
                }
            }
        }
        __syncthreads();   // smem consumed; next iter may overwrite
    }

    #pragma unroll
    for (int mt = 0; mt < 2; mt++) {
        #pragma unroll
        for (int nb = 0; nb < 6; nb++) {
            const int rowa  = row0 + mg * 32 + mt * 16 + (l >> 2);
            const int nglob = n0 + ng * 48 + nb * 8 + (l & 3) * 2;
            const int mat   = nglob >> 6;
            const int col   = nglob & 63;
            float* g = (mat == 0) ? g_Q : (mat == 1) ? g_K : g_V;
            *(float2*)&g[(size_t)rowa * HH + col] =
                make_float2(acc[mt][nb][0], acc[mt][nb][1]);
            *(float2*)&g[(size_t)(rowa + 8) * HH + col] =
                make_float2(acc[mt][nb][2], acc[mt][nb][3]);
        }
    }
}

// ---------------------------------------------------------------------------
// Kernel 2: causal flash attention, tensor cores, split-kv (2), SW-PIPELINED:
// next K/V tile prefetched into registers before the current tile's compute.
// ---------------------------------------------------------------------------
#define FSTR 66
#define PSTR 68

__global__ __launch_bounds__(128) void attn_kernel()
{
    extern __shared__ float sm[];
    float* Ksf = sm;
    float* Vsf = sm + 64 * FSTR;
    float* Ps  = sm + 2 * 64 * FSTR;

    const int tid = threadIdx.x;
    const int w   = tid >> 5;
    const int l   = tid & 31;
    const int r   = l >> 2;
    const int c   = l & 3;

    const int bid = blockIdx.x;
    const int qt  = 63 - (bid >> 3);
    const int b   = (bid >> 1) & 3;
    const int s   = bid & 1;
    const int q0  = qt * 64;
    const size_t base = (size_t)b * TT * HH;

    const int h     = (qt + 2) >> 1;
    const int ktbeg = s ? h : 0;
    const int ktend = s ? (qt + 1) : h;

    const int rowg  = q0 + w * 16 + r;
    const int rowg8 = rowg + 8;

    // per-thread staging coordinates (8 slices)
    const int jj0 = tid >> 4;            // base j for i=0
    const int hh0 = (tid & 15) << 2;     // head col

    // Q fragments in registers
    uint32_t qf[8][4];
    #pragma unroll
    for (int kb = 0; kb < 8; kb++) {
        qf[kb][0] = f2tf(0.125f * g_Q[base + (size_t)rowg  * HH + kb * 8 + c]);
        qf[kb][1] = f2tf(0.125f * g_Q[base + (size_t)rowg8 * HH + kb * 8 + c]);
        qf[kb][2] = f2tf(0.125f * g_Q[base + (size_t)rowg  * HH + kb * 8 + c + 4]);
        qf[kb][3] = f2tf(0.125f * g_Q[base + (size_t)rowg8 * HH + kb * 8 + c + 4]);
    }

    float o[8][4];
    #pragma unroll
    for (int hb = 0; hb < 8; hb++)
        o[hb][0] = o[hb][1] = o[hb][2] = o[hb][3] = 0.0f;
    float mR = -1.0e30f, mR8 = -1.0e30f, lR = 0.0f, lR8 = 0.0f;

    // prefetch registers for K/V tile
    float4 pk[8], pv[8];

    // prologue: load tile ktbeg
    #pragma unroll
    for (int i = 0; i < 8; i++) {
        const int j = jj0 + i * 8;
        const size_t g = base + (size_t)(ktbeg * 64 + j) * HH + hh0;
        pk[i] = *(const float4*)&g_K[g];
        pv[i] = *(const float4*)&g_V[g];
    }

    for (int kt = ktbeg; kt < ktend; kt++) {
        const int jbase = kt * 64;

        // ---- store prefetched K/V into fragment-native smem ----
        #pragma unroll
        for (int i = 0; i < 8; i++) {
            const int j  = jj0 + i * 8;
            const int h0 = hh0;
            {
                const int frK  = ((h0 >> 3) << 3) + (j >> 3);
                const int slot = (h0 >> 2) & 1;
                const int lb   = (j & 7) << 2;
                float* p = &Ksf[frK * FSTR + slot];
                p[(lb + 0) * 2] = __uint_as_float(f2tf(pk[i].x));
                p[(lb + 1) * 2] = __uint_as_float(f2tf(pk[i].y));
                p[(lb + 2) * 2] = __uint_as_float(f2tf(pk[i].z));
                p[(lb + 3) * 2] = __uint_as_float(f2tf(pk[i].w));
            }
            {
                const int frV  = ((j >> 3) << 3) + (h0 >> 3);
                const int slot = (j >> 2) & 1;
                const int h7   = h0 & 7;
                const int j3   = j & 3;
                float* p = &Vsf[frV * FSTR + slot];
                p[((h7 + 0) * 4 + j3) * 2] = pv[i].x;
                p[((h7 + 1) * 4 + j3) * 2] = pv[i].y;
                p[((h7 + 2) * 4 + j3) * 2] = pv[i].z;
                p[((h7 + 3) * 4 + j3) * 2] = pv[i].w;
            }
        }
        __syncthreads();

        // ---- prefetch next tile (overlaps all compute below) ----
        if (kt + 1 < ktend) {
            #pragma unroll
            for (int i = 0; i < 8; i++) {
                const int j = jj0 + i * 8;
                const size_t g = base + (size_t)((kt + 1) * 64 + j) * HH + hh0;
                pk[i] = *(const float4*)&g_K[g];
                pv[i] = *(const float4*)&g_V[g];
            }
        }

        // ---- S = Q K^T ----
        float sS[8][4];
        #pragma unroll
        for (int nb = 0; nb < 8; nb++)
            sS[nb][0] = sS[nb][1] = sS[nb][2] = sS[nb][3] = 0.0f;
        #pragma unroll
        for (int nb = 0; nb < 8; nb++)
            #pragma unroll
            for (int kb = 0; kb < 8; kb++) {
                float2 t = *(const float2*)&Ksf[(kb * 8 + nb) * FSTR + l * 2];
                mma_tf32(sS[nb], qf[kb], __float_as_uint(t.x), __float_as_uint(t.y));
            }

        if (kt == qt) {
            #pragma unroll
            for (int nb = 0; nb < 8; nb++) {
                const int col = jbase + nb * 8 + 2 * c;
                if (col     > rowg ) sS[nb][0] = -1.0e30f;
                if (col + 1 > rowg ) sS[nb][1] = -1.0e30f;
                if (col     > rowg8) sS[nb][2] = -1.0e30f;
                if (col + 1 > rowg8) sS[nb][3] = -1.0e30f;
            }
        }

        // ---- online softmax ----
        float mx0 = -1.0e30f, mx1 = -1.0e30f;
        #pragma unroll
        for (int nb = 0; nb < 8; nb++) {
            mx0 = fmaxf(mx0, fmaxf(sS[nb][0], sS[nb][1]));
            mx1 = fmaxf(mx1, fmaxf(sS[nb][2], sS[nb][3]));
        }
        mx0 = fmaxf(mx0, __shfl_xor_sync(0xffffffffu, mx0, 1));
        mx0 = fmaxf(mx0, __shfl_xor_sync(0xffffffffu, mx0, 2));
        mx1 = fmaxf(mx1, __shfl_xor_sync(0xffffffffu, mx1, 1));
        mx1 = fmaxf(mx1, __shfl_xor_sync(0xffffffffu, mx1, 2));

        const float nm0 = fmaxf(mR, mx0);
        const float nm1 = fmaxf(mR8, mx1);
        const float corr0 = __expf(mR - nm0);
        const float corr1 = __expf(mR8 - nm1);

        float sum0 = 0.0f, sum1 = 0.0f;
        #pragma unroll
        for (int nb = 0; nb < 8; nb++) {
            sS[nb][0] = __expf(sS[nb][0] - nm0);
            sS[nb][1] = __expf(sS[nb][1] - nm0);
            sS[nb][2] = __expf(sS[nb][2] - nm1);
            sS[nb][3] = __expf(sS[nb][3] - nm1);
            sum0 += sS[nb][0] + sS[nb][1];
            sum1 += sS[nb][2] + sS[nb][3];
            *(float2*)&Ps[(w * 16 + r    ) * PSTR + nb * 8 + 2 * c] =
                make_float2(sS[nb][0], sS[nb][1]);
            *(float2*)&Ps[(w * 16 + r + 8) * PSTR + nb * 8 + 2 * c] =
                make_float2(sS[nb][2], sS[nb][3]);
        }
        sum0 += __shfl_xor_sync(0xffffffffu, sum0, 1);
        sum0 += __shfl_xor_sync(0xffffffffu, sum0, 2);
        sum1 += __shfl_xor_sync(0xffffffffu, sum1, 1);
        sum1 += __shfl_xor_sync(0xffffffffu, sum1, 2);

        lR  = lR  * corr0 + sum0;  mR  = nm0;
        lR8 = lR8 * corr1 + sum1;  mR8 = nm1;
        #pragma unroll
        for (int hb = 0; hb < 8; hb++) {
            o[hb][0] *= corr0; o[hb][1] *= corr0;
            o[hb][2] *= corr1; o[hb][3] *= corr1;
        }
        __syncwarp();

        // ---- O += P @ V ----
        #pragma unroll
        for (int kb = 0; kb < 8; kb++) {
            uint32_t a[4];
            a[0] = __float_as_uint(Ps[(w * 16 + r    ) * PSTR + kb * 8 + c]);
            a[1] = __float_as_uint(Ps[(w * 16 + r + 8) * PSTR + kb * 8 + c]);
            a[2] = __float_as_uint(Ps[(w * 16 + r    ) * PSTR + kb * 8 + c + 4]);
            a[3] = __float_as_uint(Ps[(w * 16 + r + 8) * PSTR + kb * 8 + c + 4]);
            #pragma unroll
            for (int hb = 0; hb < 8; hb++) {
                float2 t = *(const float2*)&Vsf[(kb * 8 + hb) * FSTR + l * 2];
                mma_tf32(o[hb], a, __float_as_uint(t.x), __float_as_uint(t.y));
            }
        }
        __syncthreads();   // frag smem consumed; next iter overwrites
    }

    // store partials
    const size_t pr  = (size_t)(s * BB + b) * TT + rowg;
    const size_t pr8 = pr + 8;
    #pragma unroll
    for (int hb = 0; hb < 8; hb++) {
        *(float2*)&g_pO[pr  * HH + hb * 8 + 2 * c] = make_float2(o[hb][0], o[hb][1]);
        *(float2*)&g_pO[pr8 * HH + hb * 8 + 2 * c] = make_float2(o[hb][2], o[hb][3]);
    }
    if (c == 0) {
        g_pm[pr]  = mR;   g_pl[pr]  = lR;
        g_pm[pr8] = mR8;  g_pl[pr8] = lR8;
    }
}

// ---------------------------------------------------------------------------
// Kernel 3: merge the two kv-splits.
// ---------------------------------------------------------------------------
__global__ __launch_bounds__(256) void combine_kernel(float* __restrict__ out)
{
    const int gid  = blockIdx.x * 256 + threadIdx.x;
    const int rowg = gid >> 4;
    const int col  = (gid & 15) * 4;

    float m0 = g_pm[rowg],      l0 = g_pl[rowg];
    float m1 = g_pm[BT + rowg], l1 = g_pl[BT + rowg];
    float M  = fmaxf(m0, m1);
    float a0 = __expf(m0 - M);
    float a1 = __expf(m1 - M);
    float inv = 1.0f / (l0 * a0 + l1 * a1);

    float4 O0 = *(const float4*)&g_pO[(size_t)rowg * HH + col];
    float4 O1 = *(const float4*)&g_pO[(size_t)(BT + rowg) * HH + col];
    float4 o;
    o.x = (O0.x * a0 + O1.x * a1) * inv;
    o.y = (O0.y * a0 + O1.y * a1) * inv;
    o.z = (O0.z * a0 + O1.z * a1) * inv;
    o.w = (O0.w * a0 + O1.w * a1) * inv;
    *(float4*)&out[(size_t)rowg * HH + col] = o;
}

// ---------------------------------------------------------------------------
extern "C" void kernel_launch(void* const* d_in, const int* in_sizes, int n_in,
                              void* d_out, int out_size)
{
    const float* x  = (const float*)d_in[0];
    const float* Wq = (const float*)d_in[1];
    const float* Wk = (const float*)d_in[2];
    const float* Wv = (const float*)d_in[3];
    float* out = (float*)d_out;

    const int attn_smem = (2 * 64 * FSTR + 64 * PSTR) * sizeof(float);
    cudaFuncSetAttribute(attn_kernel, cudaFuncAttributeMaxDynamicSharedMemorySize,
                         attn_smem);

    prep_w<<<(DD * 192 + 255) / 256, 256>>>(Wq, Wk, Wv);
    qkv_mma<<<(BT / 128) * 2, 256>>>(x);
    attn_kernel<<<512, 128, attn_smem>>>();
    combine_kernel<<<(BT * HH / 4) / 256, 256>>>(out);
}